// round 2
// baseline (speedup 1.0000x reference)
#include <cuda_runtime.h>
#include <math.h>
#include <stdint.h>

#define VOCAB  32000
#define EMB    512
#define HID    1024
#define LABELS 64
#define NB     32
#define SEQ    512
#define MTOT   (NB * SEQ)   // 16384

// ---------------- scratch (device globals; no allocation allowed) -----------
__device__ float g_buf0[(size_t)NB * SEQ * HID];   // xp0 -> h0 (in-place)
__device__ float g_buf1[(size_t)NB * SEQ * HID];   // xp1 -> h1 (in-place)
__device__ unsigned g_bar_count = 0;
__device__ unsigned g_bar_gen   = 0;

// ---------------- GEMM: C[m,n] = sum_k A[m,k] * W[n,k] + bias --------------
// A is [M,K] row-major (or gathered emb rows when GATHER), W is [N,K] row-major.
template<int BN, int TN, bool GATHER>
__global__ void __launch_bounds__(256)
gemm_kernel(const float* __restrict__ A, const int* __restrict__ tokens,
            const float* __restrict__ W, const float* __restrict__ bias1,
            const float* __restrict__ bias2, float* __restrict__ C,
            int M, int N, int K)
{
    constexpr int BM = 128, BK = 8;
    __shared__ float As[BK][BM];
    __shared__ float Bs[BK][BN];
    __shared__ int   toks[BM];

    const int tid = threadIdx.x;
    const int bm  = blockIdx.y * BM;
    const int bn  = blockIdx.x * BN;

    constexpr int TX = BN / TN;      // 16
    const int tx = tid % TX;
    const int ty = tid / TX;         // 0..15

    if constexpr (GATHER) {
        if (tid < BM) toks[tid] = tokens[bm + tid];
    }
    __syncthreads();

    // loaders
    const int arow = tid >> 1;
    const int akq  = (tid & 1) * 4;
    const float* aptr;
    if constexpr (GATHER) aptr = A + (size_t)toks[arow] * K;
    else                  aptr = A + (size_t)(bm + arow) * K;

    const int brow = tid >> 1;
    const int bkq  = (tid & 1) * 4;
    const bool bload = (BN == 128) ? true : (tid < BN * 2);
    const float* bptr = W + (size_t)(bn + (brow < BN ? brow : 0)) * K;

    float acc[8][TN];
#pragma unroll
    for (int i = 0; i < 8; i++)
#pragma unroll
        for (int j = 0; j < TN; j++) acc[i][j] = 0.f;

    for (int k0 = 0; k0 < K; k0 += BK) {
        float4 av = *(const float4*)(aptr + k0 + akq);
        float4 bv = make_float4(0.f, 0.f, 0.f, 0.f);
        if (bload) bv = *(const float4*)(bptr + k0 + bkq);

        __syncthreads();
        As[akq + 0][arow] = av.x; As[akq + 1][arow] = av.y;
        As[akq + 2][arow] = av.z; As[akq + 3][arow] = av.w;
        if (bload) {
            Bs[bkq + 0][brow] = bv.x; Bs[bkq + 1][brow] = bv.y;
            Bs[bkq + 2][brow] = bv.z; Bs[bkq + 3][brow] = bv.w;
        }
        __syncthreads();

#pragma unroll
        for (int kk = 0; kk < BK; kk++) {
            float a[8], b[TN];
#pragma unroll
            for (int i = 0; i < 8; i++)  a[i] = As[kk][ty * 8 + i];
#pragma unroll
            for (int j = 0; j < TN; j++) b[j] = Bs[kk][tx * TN + j];
#pragma unroll
            for (int i = 0; i < 8; i++)
#pragma unroll
                for (int j = 0; j < TN; j++)
                    acc[i][j] = fmaf(a[i], b[j], acc[i][j]);
        }
    }

    float bb[TN];
#pragma unroll
    for (int j = 0; j < TN; j++) {
        int col = bn + tx * TN + j;
        bb[j] = bias1[col] + (bias2 ? bias2[col] : 0.f);
    }
#pragma unroll
    for (int i = 0; i < 8; i++) {
        int row = bm + ty * 8 + i;
#pragma unroll
        for (int j = 0; j < TN; j++)
            C[(size_t)row * N + bn + tx * TN + j] = acc[i][j] + bb[j];
    }
}

// ---------------- persistent recurrent scan --------------------------------
// grid: (4 batch-groups, 32 row-blocks) = 128 CTAs, block = 256 threads.
// buf holds xp on entry; h_t overwrites xp_t in place.
// h_t[b,j] = tanh(xp[b,t,j] + sum_k W[j,k] * h_{t-1}[b,k])
#define SCAN_NCTA   128
#define SCAN_SMEM   ((32 * 1024 + 8 * 1024 + 256 * 33) * 4)

__global__ void __launch_bounds__(256)
scan_kernel(const float* __restrict__ Whh, float* __restrict__ buf)
{
    extern __shared__ float smem[];
    float* Ws  = smem;                       // [32][1024]
    float* hs  = Ws + 32 * 1024;             // [8][1024]
    float* red = hs + 8 * 1024;              // [256][33]

    const int tid  = threadIdx.x;
    const int lane = tid & 31;
    const int warp = tid >> 5;
    const int row_base   = blockIdx.y * 32;
    const int batch_base = blockIdx.x * 8;

    // load W slice [32 rows x 1024] into smem
    {
        const float4* src = (const float4*)(Whh + (size_t)row_base * HID);
        float4* dst = (float4*)Ws;
        for (int i = tid; i < 32 * 1024 / 4; i += 256) dst[i] = src[i];
    }

    // output mapping: warp -> local batch, lane -> local row (coalesced I/O)
    const int ob   = tid >> 5;   // 0..7 local batch
    const int orow = tid & 31;   // 0..31 local row
    float* my_ptr = buf + (size_t)(batch_base + ob) * SEQ * HID + row_base + orow;

    unsigned gen = 0;
    if (tid == 0) gen = *(volatile unsigned*)&g_bar_gen;
    __syncthreads();   // Ws ready

    const int r0 = warp * 4;
    const float* wsp = Ws + (size_t)r0 * 1024;

    for (int t = 0; t < SEQ; ++t) {
        // load h_{t-1} for the 8 batches (zeros at t=0)
        if (t == 0) {
            float4 z = make_float4(0.f, 0.f, 0.f, 0.f);
            for (int i = tid; i < 8 * 1024 / 4; i += 256) ((float4*)hs)[i] = z;
        } else {
#pragma unroll
            for (int b = 0; b < 8; ++b) {
                const float4* src = (const float4*)(buf +
                    (size_t)(batch_base + b) * SEQ * HID + (size_t)(t - 1) * HID);
                ((float4*)(hs + b * 1024))[tid] = src[tid];  // 256 float4 = 1024 floats
            }
        }
        __syncthreads();

        // partial dot products: this warp owns rows r0..r0+3, lane owns k-slice
        float acc[4][8];
#pragma unroll
        for (int r = 0; r < 4; r++)
#pragma unroll
            for (int b = 0; b < 8; b++) acc[r][b] = 0.f;

#pragma unroll
        for (int g = 0; g < 8; ++g) {
            const int k4 = g * 128 + lane * 4;
            float4 wv[4], hv[8];
#pragma unroll
            for (int r = 0; r < 4; r++) wv[r] = *(const float4*)(wsp + r * 1024 + k4);
#pragma unroll
            for (int b = 0; b < 8; b++) hv[b] = *(const float4*)(hs + b * 1024 + k4);
#pragma unroll
            for (int r = 0; r < 4; r++)
#pragma unroll
                for (int b = 0; b < 8; b++) {
                    acc[r][b] = fmaf(wv[r].x, hv[b].x, acc[r][b]);
                    acc[r][b] = fmaf(wv[r].y, hv[b].y, acc[r][b]);
                    acc[r][b] = fmaf(wv[r].z, hv[b].z, acc[r][b]);
                    acc[r][b] = fmaf(wv[r].w, hv[b].w, acc[r][b]);
                }
        }

        __syncthreads();  // red free from previous step
#pragma unroll
        for (int r = 0; r < 4; r++)
#pragma unroll
            for (int b = 0; b < 8; b++)
                red[(b * 32 + r0 + r) * 33 + lane] = acc[r][b];
        __syncthreads();

        // reduce 32 lane-partials for output index tid = ob*32 + orow
        float s = 0.f;
#pragma unroll
        for (int j = 0; j < 32; j++) s += red[tid * 33 + j];

        float xv = my_ptr[(size_t)t * HID];              // xp (own slot, first touch)
        float h  = tanhf(xv + s);
        my_ptr[(size_t)t * HID] = h;                     // overwrite in place

        // grid-wide barrier (except after last step)
        if (t < SEQ - 1) {
            __syncthreads();
            if (tid == 0) {
                __threadfence();
                unsigned arr = atomicAdd(&g_bar_count, 1u);
                if (arr == SCAN_NCTA - 1) {
                    atomicExch(&g_bar_count, 0u);
                    __threadfence();
                    atomicExch(&g_bar_gen, gen + 1u);
                } else {
                    while (*(volatile unsigned*)&g_bar_gen == gen) { }
                }
                gen = gen + 1u;
                __threadfence();
            }
            __syncthreads();
        }
    }
}

// ---------------- host launcher --------------------------------------------
extern "C" void kernel_launch(void* const* d_in, const int* in_sizes, int n_in,
                              void* d_out, int out_size)
{
    const int*   tokens = (const int*)  d_in[0];
    const float* emb    = (const float*)d_in[1];
    const float* W_ih0  = (const float*)d_in[2];
    const float* W_hh0  = (const float*)d_in[3];
    const float* b_ih0  = (const float*)d_in[4];
    const float* b_hh0  = (const float*)d_in[5];
    const float* W_ih1  = (const float*)d_in[6];
    const float* W_hh1  = (const float*)d_in[7];
    const float* b_ih1  = (const float*)d_in[8];
    const float* b_hh1  = (const float*)d_in[9];
    const float* W_out  = (const float*)d_in[10];
    const float* b_out  = (const float*)d_in[11];
    float* out = (float*)d_out;

    float *buf0, *buf1;
    cudaGetSymbolAddress((void**)&buf0, g_buf0);
    cudaGetSymbolAddress((void**)&buf1, g_buf1);

    cudaFuncSetAttribute(scan_kernel,
        cudaFuncAttributeMaxDynamicSharedMemorySize, SCAN_SMEM);

    dim3 gproj(HID / 128, MTOT / 128);   // (8, 128)
    dim3 gout(1, MTOT / 128);            // (1, 128)
    dim3 gscan(4, 32);                   // 128 CTAs

    // layer 0: xp0 = gather(emb, tokens) @ W_ih0^T + (b_ih0 + b_hh0)
    gemm_kernel<128, 8, true ><<<gproj, 256>>>(emb, tokens, W_ih0, b_ih0, b_hh0,
                                               buf0, MTOT, HID, EMB);
    scan_kernel<<<gscan, 256, SCAN_SMEM>>>(W_hh0, buf0);

    // layer 1: xp1 = h0 @ W_ih1^T + (b_ih1 + b_hh1)
    gemm_kernel<128, 8, false><<<gproj, 256>>>(buf0, nullptr, W_ih1, b_ih1, b_hh1,
                                               buf1, MTOT, HID, HID);
    scan_kernel<<<gscan, 256, SCAN_SMEM>>>(W_hh1, buf1);

    // output: out = h1 @ W_out^T + b_out
    gemm_kernel<64, 4, false><<<gout, 256>>>(buf1, nullptr, W_out, b_out, nullptr,
                                             out, MTOT, LABELS, HID);
}

// round 4
// speedup vs baseline: 1.4774x; 1.4774x over previous
#include <cuda_runtime.h>
#include <math.h>
#include <stdint.h>

#define VOCAB  32000
#define EMB    512
#define HID    1024
#define LABELS 64
#define NB     32
#define SEQ    512
#define MTOT   (NB * SEQ)   // 16384

// ---------------- scratch (device globals; no allocation allowed) -----------
__device__ float g_buf0[(size_t)NB * SEQ * HID];   // xp0 -> h0 (in-place)
__device__ float g_buf1[(size_t)NB * SEQ * HID];   // xp1 -> h1 (in-place)
__device__ unsigned g_cnt0;
__device__ unsigned g_cnt1;

__global__ void reset_kernel(unsigned* c0, unsigned* c1) { *c0 = 0u; *c1 = 0u; }

// ---------------- 3xTF32 tensor-core GEMM -----------------------------------
// C[m,n] = sum_k A[m,k] * W[n,k] + bias   (A row-major [M,K], W row-major [N,K])
// Each operand split hi/lo in tf32; acc += Ahi*Bhi + Alo*Bhi + Ahi*Blo  (~fp32).
__device__ __forceinline__ uint32_t f2tf32(float x)
{
    uint32_t r;
    asm("cvt.rna.tf32.f32 %0, %1;" : "=r"(r) : "f"(x));
    return r;
}

__device__ __forceinline__ void mma_tf32(float* d, const uint32_t* a, const uint32_t* b)
{
    asm volatile(
        "mma.sync.aligned.m16n8k8.row.col.f32.tf32.tf32.f32 "
        "{%0,%1,%2,%3},{%4,%5,%6,%7},{%8,%9},{%0,%1,%2,%3};"
        : "+f"(d[0]), "+f"(d[1]), "+f"(d[2]), "+f"(d[3])
        : "r"(a[0]), "r"(a[1]), "r"(a[2]), "r"(a[3]), "r"(b[0]), "r"(b[1]));
}

template<int BM, int BN, bool GATHER>
__global__ void __launch_bounds__((BM / 64) * (BN / 32) * 32)
gemm_tf32(const float* __restrict__ A, const int* __restrict__ tokens,
          const float* __restrict__ W, const float* __restrict__ bias1,
          const float* __restrict__ bias2, float* __restrict__ C,
          int N, int K)
{
    constexpr int BK = 32;
    constexpr int NWX = BN / 32;             // warps along n
    constexpr int NW  = (BM / 64) * NWX;     // total warps
    constexpr int T   = NW * 32;             // threads
    constexpr int LDA = BM * 8 / T;          // float4 loads per thread (A)
    constexpr int LDB = BN * 8 / T;          // float4 loads per thread (B)

    __shared__ float As[BM][36];
    __shared__ float Bs[BN][36];
    __shared__ int   toks[BM];

    const int tid  = threadIdx.x;
    const int lane = tid & 31;
    const int warp = tid >> 5;
    const int wy   = warp / NWX;             // warp m-index (WM=64)
    const int wx   = warp % NWX;             // warp n-index (WN=32)
    const int gr   = lane >> 2;              // groupID
    const int gc   = lane & 3;               // threadID_in_group

    const int bm = blockIdx.y * BM;
    const int bn = blockIdx.x * BN;

    if constexpr (GATHER) {
        if (tid < BM) toks[tid] = tokens[bm + tid];
        __syncthreads();
    }

    float4 aR[LDA], bR[LDB];
    auto loadA = [&](int k0) {
#pragma unroll
        for (int i = 0; i < LDA; i++) {
            int idx = tid + i * T;
            int row = idx >> 3, kq = (idx & 7) * 4;
            const float* p;
            if constexpr (GATHER) p = A + (size_t)toks[row] * K;
            else                  p = A + (size_t)(bm + row) * K;
            aR[i] = *(const float4*)(p + k0 + kq);
        }
    };
    auto loadB = [&](int k0) {
#pragma unroll
        for (int i = 0; i < LDB; i++) {
            int idx = tid + i * T;
            int row = idx >> 3, kq = (idx & 7) * 4;
            bR[i] = *(const float4*)(W + (size_t)(bn + row) * K + k0 + kq);
        }
    };

    float acc[4][4][4];
#pragma unroll
    for (int i = 0; i < 4; i++)
#pragma unroll
        for (int j = 0; j < 4; j++)
#pragma unroll
            for (int r = 0; r < 4; r++) acc[i][j][r] = 0.f;

    loadA(0); loadB(0);
    const int iters = K / BK;

    for (int it = 0; it < iters; ++it) {
        __syncthreads();
#pragma unroll
        for (int i = 0; i < LDA; i++) {
            int idx = tid + i * T;
            int row = idx >> 3, kq = (idx & 7) * 4;
            *(float4*)&As[row][kq] = aR[i];
        }
#pragma unroll
        for (int i = 0; i < LDB; i++) {
            int idx = tid + i * T;
            int row = idx >> 3, kq = (idx & 7) * 4;
            *(float4*)&Bs[row][kq] = bR[i];
        }
        __syncthreads();

        if (it + 1 < iters) { loadA((it + 1) * BK); loadB((it + 1) * BK); }

#pragma unroll
        for (int s = 0; s < 4; ++s) {
            uint32_t ah[4][4], al[4][4], bh[4][2], bl[4][2];
#pragma unroll
            for (int i = 0; i < 4; i++) {
                int row = wy * 64 + i * 16 + gr;
                int col = s * 8 + gc;
                float v0 = As[row    ][col    ];
                float v1 = As[row + 8][col    ];
                float v2 = As[row    ][col + 4];
                float v3 = As[row + 8][col + 4];
                ah[i][0] = f2tf32(v0); al[i][0] = f2tf32(v0 - __uint_as_float(ah[i][0]));
                ah[i][1] = f2tf32(v1); al[i][1] = f2tf32(v1 - __uint_as_float(ah[i][1]));
                ah[i][2] = f2tf32(v2); al[i][2] = f2tf32(v2 - __uint_as_float(ah[i][2]));
                ah[i][3] = f2tf32(v3); al[i][3] = f2tf32(v3 - __uint_as_float(ah[i][3]));
            }
#pragma unroll
            for (int j = 0; j < 4; j++) {
                int nrow = wx * 32 + j * 8 + gr;
                int col  = s * 8 + gc;
                float v0 = Bs[nrow][col    ];
                float v1 = Bs[nrow][col + 4];
                bh[j][0] = f2tf32(v0); bl[j][0] = f2tf32(v0 - __uint_as_float(bh[j][0]));
                bh[j][1] = f2tf32(v1); bl[j][1] = f2tf32(v1 - __uint_as_float(bh[j][1]));
            }
#pragma unroll
            for (int i = 0; i < 4; i++)
#pragma unroll
                for (int j = 0; j < 4; j++) {
                    mma_tf32(acc[i][j], al[i], bh[j]);   // lo*hi
                    mma_tf32(acc[i][j], ah[i], bl[j]);   // hi*lo
                    mma_tf32(acc[i][j], ah[i], bh[j]);   // hi*hi (last: largest term)
                }
        }
    }

    // bias per n-tile: cols c0 = gc*2, c0+1
    float bs[4][2];
#pragma unroll
    for (int j = 0; j < 4; j++) {
        int c = bn + wx * 32 + j * 8 + gc * 2;
        bs[j][0] = bias1[c]     + (bias2 ? bias2[c]     : 0.f);
        bs[j][1] = bias1[c + 1] + (bias2 ? bias2[c + 1] : 0.f);
    }
#pragma unroll
    for (int i = 0; i < 4; i++) {
        int r0 = bm + wy * 64 + i * 16 + gr;
#pragma unroll
        for (int j = 0; j < 4; j++) {
            int c = bn + wx * 32 + j * 8 + gc * 2;
            float2 v0 = make_float2(acc[i][j][0] + bs[j][0], acc[i][j][1] + bs[j][1]);
            float2 v1 = make_float2(acc[i][j][2] + bs[j][0], acc[i][j][3] + bs[j][1]);
            *(float2*)&C[(size_t)r0 * N + c]       = v0;
            *(float2*)&C[(size_t)(r0 + 8) * N + c] = v1;
        }
    }
}

// ---------------- persistent recurrent scan --------------------------------
// grid: (4 batch-groups, 32 row-blocks) = 128 CTAs, block = 256 threads.
// buf holds xp on entry; h_t overwrites xp_t in place.
// h_t[b,j] = tanh(xp[b,t,j] + sum_k W[j,k] * h_{t-1}[b,k])
#define SCAN_NCTA   128
#define SCAN_SMEM   ((32 * 1024 + 8 * 1024 + 256 * 33) * 4)

__global__ void __launch_bounds__(256)
scan_kernel(const float* __restrict__ Whh, float* __restrict__ buf,
            unsigned* __restrict__ cnt)
{
    extern __shared__ float smem[];
    float* Ws  = smem;                       // [32][1024]
    float* hs  = Ws + 32 * 1024;             // [8][1024]
    float* red = hs + 8 * 1024;              // [256][33]

    const int tid  = threadIdx.x;
    const int lane = tid & 31;
    const int warp = tid >> 5;
    const int row_base   = blockIdx.y * 32;
    const int batch_base = blockIdx.x * 8;

    // load W slice [32 rows x 1024] into smem
    {
        const float4* src = (const float4*)(Whh + (size_t)row_base * HID);
        float4* dst = (float4*)Ws;
        for (int i = tid; i < 32 * 1024 / 4; i += 256) dst[i] = src[i];
    }

    // output mapping: warp -> local batch, lane -> local row (coalesced I/O)
    const int ob   = tid >> 5;
    const int orow = tid & 31;
    float* my_ptr = buf + (size_t)(batch_base + ob) * SEQ * HID + row_base + orow;

    __syncthreads();   // Ws ready

    const int r0 = warp * 4;
    const float* wsp = Ws + (size_t)r0 * 1024;

    for (int t = 0; t < SEQ; ++t) {
        // load h_{t-1} for the 8 batches (zeros at t=0)
        if (t == 0) {
            float4 z = make_float4(0.f, 0.f, 0.f, 0.f);
            for (int i = tid; i < 8 * 1024 / 4; i += 256) ((float4*)hs)[i] = z;
        } else {
#pragma unroll
            for (int b = 0; b < 8; ++b) {
                const float4* src = (const float4*)(buf +
                    (size_t)(batch_base + b) * SEQ * HID + (size_t)(t - 1) * HID);
                ((float4*)(hs + b * 1024))[tid] = src[tid];
            }
        }
        float xv = my_ptr[(size_t)t * HID];   // prefetch xp (own slot, first touch)
        __syncthreads();

        // partial dot products: this warp owns rows r0..r0+3, lane owns k-slice
        float acc[4][8];
#pragma unroll
        for (int r = 0; r < 4; r++)
#pragma unroll
            for (int b = 0; b < 8; b++) acc[r][b] = 0.f;

#pragma unroll
        for (int g = 0; g < 8; ++g) {
            const int k4 = g * 128 + lane * 4;
            float4 wv[4], hv[8];
#pragma unroll
            for (int r = 0; r < 4; r++) wv[r] = *(const float4*)(wsp + r * 1024 + k4);
#pragma unroll
            for (int b = 0; b < 8; b++) hv[b] = *(const float4*)(hs + b * 1024 + k4);
#pragma unroll
            for (int r = 0; r < 4; r++)
#pragma unroll
                for (int b = 0; b < 8; b++) {
                    acc[r][b] = fmaf(wv[r].x, hv[b].x, acc[r][b]);
                    acc[r][b] = fmaf(wv[r].y, hv[b].y, acc[r][b]);
                    acc[r][b] = fmaf(wv[r].z, hv[b].z, acc[r][b]);
                    acc[r][b] = fmaf(wv[r].w, hv[b].w, acc[r][b]);
                }
        }

        __syncthreads();  // red free from previous step
#pragma unroll
        for (int r = 0; r < 4; r++)
#pragma unroll
            for (int b = 0; b < 8; b++)
                red[(b * 32 + r0 + r) * 33 + lane] = acc[r][b];
        __syncthreads();

        // reduce 32 lane-partials for output index tid = ob*32 + orow
        float s = 0.f;
#pragma unroll
        for (int j = 0; j < 32; j++) s += red[tid * 33 + j];

        float h = tanhf(xv + s);
        my_ptr[(size_t)t * HID] = h;          // overwrite in place

        // grid-wide barrier: no-return red + monotonic-count acquire polling
        if (t < SEQ - 1) {
            __syncthreads();
            if (tid == 0) {
                asm volatile("red.release.gpu.global.add.u32 [%0], 1;"
                             :: "l"(cnt) : "memory");
                const unsigned target = (unsigned)(t + 1) * SCAN_NCTA;
                unsigned v;
                do {
                    asm volatile("ld.acquire.gpu.global.u32 %0, [%1];"
                                 : "=r"(v) : "l"(cnt) : "memory");
                } while (v < target);
            }
            __syncthreads();
        }
    }
}

// ---------------- host launcher --------------------------------------------
extern "C" void kernel_launch(void* const* d_in, const int* in_sizes, int n_in,
                              void* d_out, int out_size)
{
    const int*   tokens = (const int*)  d_in[0];
    const float* emb    = (const float*)d_in[1];
    const float* W_ih0  = (const float*)d_in[2];
    const float* W_hh0  = (const float*)d_in[3];
    const float* b_ih0  = (const float*)d_in[4];
    const float* b_hh0  = (const float*)d_in[5];
    const float* W_ih1  = (const float*)d_in[6];
    const float* W_hh1  = (const float*)d_in[7];
    const float* b_ih1  = (const float*)d_in[8];
    const float* b_hh1  = (const float*)d_in[9];
    const float* W_out  = (const float*)d_in[10];
    const float* b_out  = (const float*)d_in[11];
    float* out = (float*)d_out;

    float *buf0, *buf1;
    unsigned *c0, *c1;
    cudaGetSymbolAddress((void**)&buf0, g_buf0);
    cudaGetSymbolAddress((void**)&buf1, g_buf1);
    cudaGetSymbolAddress((void**)&c0, g_cnt0);
    cudaGetSymbolAddress((void**)&c1, g_cnt1);

    cudaFuncSetAttribute(scan_kernel,
        cudaFuncAttributeMaxDynamicSharedMemorySize, SCAN_SMEM);

    dim3 gproj(HID / 128, MTOT / 128);   // (8, 128)
    dim3 gout(1, MTOT / 128);            // (1, 128)
    dim3 gscan(4, 32);                   // 128 CTAs

    reset_kernel<<<1, 1>>>(c0, c1);

    // layer 0: xp0 = gather(emb, tokens) @ W_ih0^T + (b_ih0 + b_hh0)
    gemm_tf32<128, 128, true ><<<gproj, 256>>>(emb, tokens, W_ih0, b_ih0, b_hh0,
                                               buf0, HID, EMB);
    scan_kernel<<<gscan, 256, SCAN_SMEM>>>(W_hh0, buf0, c0);

    // layer 1: xp1 = h0 @ W_ih1^T + (b_ih1 + b_hh1)
    gemm_tf32<128, 128, false><<<gproj, 256>>>(buf0, nullptr, W_ih1, b_ih1, b_hh1,
                                               buf1, HID, HID);
    scan_kernel<<<gscan, 256, SCAN_SMEM>>>(W_hh1, buf1, c1);

    // output: out = h1 @ W_out^T + b_out
    gemm_tf32<128, 64, false><<<gout, 128>>>(buf1, nullptr, W_out, b_out, nullptr,
                                             out, LABELS, HID);
}

// round 6
// speedup vs baseline: 1.6132x; 1.0920x over previous
#include <cuda_runtime.h>
#include <math.h>
#include <stdint.h>

#define VOCAB  32000
#define EMB    512
#define HID    1024
#define LABELS 64
#define NB     32
#define SEQ    512
#define MTOT   (NB * SEQ)   // 16384

// ---------------- scratch (device globals; no allocation allowed) -----------
__device__ float g_buf0[(size_t)NB * SEQ * HID];   // xp0 -> h0 (in-place)
__device__ float g_buf1[(size_t)NB * SEQ * HID];   // xp1 -> h1 (in-place)
__device__ unsigned g_cnt0;
__device__ unsigned g_cnt1;

__global__ void reset_kernel(unsigned* c0, unsigned* c1) { *c0 = 0u; *c1 = 0u; }

// ---------------- tf32 helpers ----------------------------------------------
__device__ __forceinline__ uint32_t f2tf32(float x)
{
    uint32_t r;
    asm("cvt.rna.tf32.f32 %0, %1;" : "=r"(r) : "f"(x));
    return r;
}

__device__ __forceinline__ void mma_tf32(float* d, const uint32_t* a, const uint32_t* b)
{
    asm volatile(
        "mma.sync.aligned.m16n8k8.row.col.f32.tf32.tf32.f32 "
        "{%0,%1,%2,%3},{%4,%5,%6,%7},{%8,%9},{%0,%1,%2,%3};"
        : "+f"(d[0]), "+f"(d[1]), "+f"(d[2]), "+f"(d[3])
        : "r"(a[0]), "r"(a[1]), "r"(a[2]), "r"(a[3]), "r"(b[0]), "r"(b[1]));
}

// ---------------- 3xTF32 tensor-core GEMM -----------------------------------
// C[m,n] = sum_k A[m,k] * W[n,k] + bias   (A row-major [M,K], W row-major [N,K])
template<int BM, int BN, bool GATHER>
__global__ void __launch_bounds__((BM / 64) * (BN / 32) * 32)
gemm_tf32(const float* __restrict__ A, const int* __restrict__ tokens,
          const float* __restrict__ W, const float* __restrict__ bias1,
          const float* __restrict__ bias2, float* __restrict__ C,
          int N, int K)
{
    constexpr int BK = 32;
    constexpr int NWX = BN / 32;
    constexpr int NW  = (BM / 64) * NWX;
    constexpr int T   = NW * 32;
    constexpr int LDA = BM * 8 / T;
    constexpr int LDB = BN * 8 / T;

    __shared__ float As[BM][36];
    __shared__ float Bs[BN][36];
    __shared__ int   toks[BM];

    const int tid  = threadIdx.x;
    const int lane = tid & 31;
    const int warp = tid >> 5;
    const int wy   = warp / NWX;
    const int wx   = warp % NWX;
    const int gr   = lane >> 2;
    const int gc   = lane & 3;

    const int bm = blockIdx.y * BM;
    const int bn = blockIdx.x * BN;

    if constexpr (GATHER) {
        if (tid < BM) toks[tid] = tokens[bm + tid];
        __syncthreads();
    }

    float4 aR[LDA], bR[LDB];
    auto loadA = [&](int k0) {
#pragma unroll
        for (int i = 0; i < LDA; i++) {
            int idx = tid + i * T;
            int row = idx >> 3, kq = (idx & 7) * 4;
            const float* p;
            if constexpr (GATHER) p = A + (size_t)toks[row] * K;
            else                  p = A + (size_t)(bm + row) * K;
            aR[i] = *(const float4*)(p + k0 + kq);
        }
    };
    auto loadB = [&](int k0) {
#pragma unroll
        for (int i = 0; i < LDB; i++) {
            int idx = tid + i * T;
            int row = idx >> 3, kq = (idx & 7) * 4;
            bR[i] = *(const float4*)(W + (size_t)(bn + row) * K + k0 + kq);
        }
    };

    float acc[4][4][4];
#pragma unroll
    for (int i = 0; i < 4; i++)
#pragma unroll
        for (int j = 0; j < 4; j++)
#pragma unroll
            for (int r = 0; r < 4; r++) acc[i][j][r] = 0.f;

    loadA(0); loadB(0);
    const int iters = K / BK;

    for (int it = 0; it < iters; ++it) {
        __syncthreads();
#pragma unroll
        for (int i = 0; i < LDA; i++) {
            int idx = tid + i * T;
            int row = idx >> 3, kq = (idx & 7) * 4;
            *(float4*)&As[row][kq] = aR[i];
        }
#pragma unroll
        for (int i = 0; i < LDB; i++) {
            int idx = tid + i * T;
            int row = idx >> 3, kq = (idx & 7) * 4;
            *(float4*)&Bs[row][kq] = bR[i];
        }
        __syncthreads();

        if (it + 1 < iters) { loadA((it + 1) * BK); loadB((it + 1) * BK); }

#pragma unroll
        for (int s = 0; s < 4; ++s) {
            uint32_t ah[4][4], al[4][4], bh[4][2], bl[4][2];
#pragma unroll
            for (int i = 0; i < 4; i++) {
                int row = wy * 64 + i * 16 + gr;
                int col = s * 8 + gc;
                float v0 = As[row    ][col    ];
                float v1 = As[row + 8][col    ];
                float v2 = As[row    ][col + 4];
                float v3 = As[row + 8][col + 4];
                ah[i][0] = f2tf32(v0); al[i][0] = f2tf32(v0 - __uint_as_float(ah[i][0]));
                ah[i][1] = f2tf32(v1); al[i][1] = f2tf32(v1 - __uint_as_float(ah[i][1]));
                ah[i][2] = f2tf32(v2); al[i][2] = f2tf32(v2 - __uint_as_float(ah[i][2]));
                ah[i][3] = f2tf32(v3); al[i][3] = f2tf32(v3 - __uint_as_float(ah[i][3]));
            }
#pragma unroll
            for (int j = 0; j < 4; j++) {
                int nrow = wx * 32 + j * 8 + gr;
                int col  = s * 8 + gc;
                float v0 = Bs[nrow][col    ];
                float v1 = Bs[nrow][col + 4];
                bh[j][0] = f2tf32(v0); bl[j][0] = f2tf32(v0 - __uint_as_float(bh[j][0]));
                bh[j][1] = f2tf32(v1); bl[j][1] = f2tf32(v1 - __uint_as_float(bh[j][1]));
            }
#pragma unroll
            for (int i = 0; i < 4; i++)
#pragma unroll
                for (int j = 0; j < 4; j++) {
                    mma_tf32(acc[i][j], al[i], bh[j]);
                    mma_tf32(acc[i][j], ah[i], bl[j]);
                    mma_tf32(acc[i][j], ah[i], bh[j]);
                }
        }
    }

    float bs[4][2];
#pragma unroll
    for (int j = 0; j < 4; j++) {
        int c = bn + wx * 32 + j * 8 + gc * 2;
        bs[j][0] = bias1[c]     + (bias2 ? bias2[c]     : 0.f);
        bs[j][1] = bias1[c + 1] + (bias2 ? bias2[c + 1] : 0.f);
    }
#pragma unroll
    for (int i = 0; i < 4; i++) {
        int r0 = bm + wy * 64 + i * 16 + gr;
#pragma unroll
        for (int j = 0; j < 4; j++) {
            int c = bn + wx * 32 + j * 8 + gc * 2;
            float2 v0 = make_float2(acc[i][j][0] + bs[j][0], acc[i][j][1] + bs[j][1]);
            float2 v1 = make_float2(acc[i][j][2] + bs[j][0], acc[i][j][3] + bs[j][1]);
            *(float2*)&C[(size_t)r0 * N + c]       = v0;
            *(float2*)&C[(size_t)(r0 + 8) * N + c] = v1;
        }
    }
}

// ---------------- persistent MMA recurrent scan ------------------------------
// grid: (2 batch-groups of 16, 64 row-blocks of 16) = 128 CTAs, 256 threads.
// buf holds xp on entry; h_t overwrites xp_t in place.
// Per CTA: D[16 rows x 16 batches] = W_slice[16 x 1024] * h^T, 3xTF32 MMA,
// K split across 8 warps (128 each), W fragments resident in registers.
#define SCAN_NCTA   128
#define HS_LD       1028                       // 1024 + 4 pad (bank spread)
#define RED_LD      9                          // 8 warps + 1 pad
#define SCAN_SMEM   ((16 * HS_LD + 256 * RED_LD) * 4)

__global__ void __launch_bounds__(256, 1)
scan_mma(const float* __restrict__ Whh, float* __restrict__ buf,
         unsigned* __restrict__ cnt)
{
    extern __shared__ float smem[];
    float* hs  = smem;                         // [16][HS_LD]
    float* red = smem + 16 * HS_LD;            // [256][RED_LD]

    const int tid  = threadIdx.x;
    const int lane = tid & 31;
    const int warp = tid >> 5;
    const int gr   = lane >> 2;                // 0..7
    const int gc   = lane & 3;                 // 0..3
    const int kw   = warp * 128;               // this warp's K slice

    const int batch_base = blockIdx.x * 16;    // 0 or 16
    const int row_base   = blockIdx.y * 16;    // 0..1008

    // ---- preload W fragments (hi/lo tf32) into registers, once -------------
    uint32_t whi[16][4], wlo[16][4];
#pragma unroll
    for (int kt = 0; kt < 16; kt++) {
#pragma unroll
        for (int q = 0; q < 4; q++) {
            int r = row_base + gr + ((q & 1) ? 8 : 0);
            int k = kw + kt * 8 + gc + ((q >= 2) ? 4 : 0);
            float w = Whh[(size_t)r * HID + k];
            whi[kt][q] = f2tf32(w);
            wlo[kt][q] = f2tf32(w - __uint_as_float(whi[kt][q]));
        }
    }

    // ---- output mapping: o = tid, b = o>>4, r = o&15 (coalesced 64B runs) ---
    const int ob   = tid >> 4;
    const int orow = tid & 15;
    const size_t my_base = (size_t)(batch_base + ob) * SEQ * HID + row_base + orow;

    // zero hs (h_{-1} = 0)
    {
        float4 z = make_float4(0.f, 0.f, 0.f, 0.f);
        for (int i = tid; i < 16 * HS_LD / 4; i += 256) ((float4*)hs)[i] = z;
    }

    const float* gbase = buf + (size_t)batch_base * SEQ * HID;

    for (int t = 0; t < SEQ; ++t) {
        // ---- stage h_{t-1} into smem (L1-bypass; other CTAs wrote it) -------
        // 16 batches x 256 float4 each; iteration j loads batch j contiguously
        // (kq = tid*4 -> perfectly coalesced 4KB per batch).
        if (t > 0) {
            const float* src = gbase + (size_t)(t - 1) * HID;
#pragma unroll
            for (int j = 0; j < 16; j++) {
                int i  = tid + 256 * j;
                int b  = i >> 8;             // 0..15  (256 float4 per batch)
                int kq = (i & 255) * 4;      // 0..1020
                float4 v = __ldcg((const float4*)(src + (size_t)b * SEQ * HID + kq));
                *(float4*)&hs[b * HS_LD + kq] = v;
            }
        }
        float xv = __ldcg(buf + my_base + (size_t)t * HID);   // own xp slot
        __syncthreads();

        // ---- MMA: 1 m-tile x 2 n-tiles x 16 k-tiles x 3 passes --------------
        float acc[2][4];
#pragma unroll
        for (int j = 0; j < 2; j++)
#pragma unroll
            for (int q = 0; q < 4; q++) acc[j][q] = 0.f;

#pragma unroll
        for (int kt = 0; kt < 16; kt++) {
            uint32_t bh[2][2], bl[2][2];
#pragma unroll
            for (int j = 0; j < 2; j++) {
                const float* hr = hs + (j * 8 + gr) * HS_LD + kw + kt * 8 + gc;
                float v0 = hr[0];
                float v1 = hr[4];
                bh[j][0] = f2tf32(v0); bl[j][0] = f2tf32(v0 - __uint_as_float(bh[j][0]));
                bh[j][1] = f2tf32(v1); bl[j][1] = f2tf32(v1 - __uint_as_float(bh[j][1]));
            }
#pragma unroll
            for (int j = 0; j < 2; j++) {
                mma_tf32(acc[j], wlo[kt], bh[j]);
                mma_tf32(acc[j], whi[kt], bl[j]);
                mma_tf32(acc[j], whi[kt], bh[j]);
            }
        }

        // ---- cross-warp K reduction ----------------------------------------
        // D[r= gr(+8)][b= j*8 + 2gc(+1)];  red[(b*16+r)*RED_LD + warp]
#pragma unroll
        for (int j = 0; j < 2; j++) {
            int b0 = j * 8 + 2 * gc;
            red[((b0    ) * 16 + gr    ) * RED_LD + warp] = acc[j][0];
            red[((b0 + 1) * 16 + gr    ) * RED_LD + warp] = acc[j][1];
            red[((b0    ) * 16 + gr + 8) * RED_LD + warp] = acc[j][2];
            red[((b0 + 1) * 16 + gr + 8) * RED_LD + warp] = acc[j][3];
        }
        __syncthreads();

        float s = 0.f;
#pragma unroll
        for (int w2 = 0; w2 < 8; w2++) s += red[tid * RED_LD + w2];

        float h = tanhf(xv + s);
        buf[my_base + (size_t)t * HID] = h;      // overwrite xp in place

        // ---- grid barrier (release red + monotonic acquire poll) -----------
        if (t < SEQ - 1) {
            __syncthreads();
            if (tid == 0) {
                asm volatile("red.release.gpu.global.add.u32 [%0], 1;"
                             :: "l"(cnt) : "memory");
                const unsigned target = (unsigned)(t + 1) * SCAN_NCTA;
                unsigned v;
                do {
                    asm volatile("ld.acquire.gpu.global.u32 %0, [%1];"
                                 : "=r"(v) : "l"(cnt) : "memory");
                } while (v < target);
            }
            __syncthreads();
        }
    }
}

// ---------------- host launcher ---------------------------------------------
extern "C" void kernel_launch(void* const* d_in, const int* in_sizes, int n_in,
                              void* d_out, int out_size)
{
    const int*   tokens = (const int*)  d_in[0];
    const float* emb    = (const float*)d_in[1];
    const float* W_ih0  = (const float*)d_in[2];
    const float* W_hh0  = (const float*)d_in[3];
    const float* b_ih0  = (const float*)d_in[4];
    const float* b_hh0  = (const float*)d_in[5];
    const float* W_ih1  = (const float*)d_in[6];
    const float* W_hh1  = (const float*)d_in[7];
    const float* b_ih1  = (const float*)d_in[8];
    const float* b_hh1  = (const float*)d_in[9];
    const float* W_out  = (const float*)d_in[10];
    const float* b_out  = (const float*)d_in[11];
    float* out = (float*)d_out;

    float *buf0, *buf1;
    unsigned *c0, *c1;
    cudaGetSymbolAddress((void**)&buf0, g_buf0);
    cudaGetSymbolAddress((void**)&buf1, g_buf1);
    cudaGetSymbolAddress((void**)&c0, g_cnt0);
    cudaGetSymbolAddress((void**)&c1, g_cnt1);

    cudaFuncSetAttribute(scan_mma,
        cudaFuncAttributeMaxDynamicSharedMemorySize, SCAN_SMEM);

    dim3 gproj(HID / 128, MTOT / 128);   // (8, 128)
    dim3 gout(1, MTOT / 128);            // (1, 128)
    dim3 gscan(2, 64);                   // 128 CTAs

    reset_kernel<<<1, 1>>>(c0, c1);

    // layer 0: xp0 = gather(emb, tokens) @ W_ih0^T + (b_ih0 + b_hh0)
    gemm_tf32<128, 128, true ><<<gproj, 256>>>(emb, tokens, W_ih0, b_ih0, b_hh0,
                                               buf0, HID, EMB);
    scan_mma<<<gscan, 256, SCAN_SMEM>>>(W_hh0, buf0, c0);

    // layer 1: xp1 = h0 @ W_ih1^T + (b_ih1 + b_hh1)
    gemm_tf32<128, 128, false><<<gproj, 256>>>(buf0, nullptr, W_ih1, b_ih1, b_hh1,
                                               buf1, HID, HID);
    scan_mma<<<gscan, 256, SCAN_SMEM>>>(W_hh1, buf1, c1);

    // output: out = h1 @ W_out^T + b_out
    gemm_tf32<128, 64, false><<<gout, 128>>>(buf1, nullptr, W_out, b_out, nullptr,
                                             out, LABELS, HID);
}